// round 14
// baseline (speedup 1.0000x reference)
#include <cuda_runtime.h>
#include <math.h>

#define B_   128
#define P_   2048
#define NB_  2000
#define NF_  250
#define NC_  16
#define R_   128
#define LS_  1750      // NB - NF
#define FT_  1751      // NB - NF + 1
#define NW_  63        // 32-bit words covering NB=2000
#define NWP_ 64        // padded row stride in words
#define BCH_ 64        // b's per chunk (2 chunks)

// ---------------- scratch (static device globals; no allocations) ----------------
__device__ float d_filt[FT_];
__device__ float d_stimdot[B_];
__device__ float d_gensig[B_ * LS_];
__device__ unsigned d_bm[B_ * NC_ * NWP_];   // bitmask of cc != 0

// ---------------- K-small: filt + stimdot (one warp per t / per b) ----------------
#define FILT_WARPS FT_
#define SMALL_WARPS (FILT_WARPS + B_)
__global__ void __launch_bounds__(256)
k_small(const float* __restrict__ stim_time,
        const float* __restrict__ stf,
        const float* __restrict__ spat,
        const float* __restrict__ sf) {
    int warp = (blockIdx.x * blockDim.x + threadIdx.x) >> 5;
    int lane = threadIdx.x & 31;
    if (warp < FILT_WARPS) {
        double a = 0.0;
        #pragma unroll
        for (int i = lane; i < NF_; i += 32)
            a += (double)stim_time[warp + i] * (double)stf[i];
        #pragma unroll
        for (int m = 16; m; m >>= 1) a += __shfl_xor_sync(0xffffffffu, a, m);
        if (lane == 0) d_filt[warp] = (float)a;
    } else if (warp < SMALL_WARPS) {
        int b = warp - FILT_WARPS;
        const float* row = spat + (size_t)b * P_;
        double a = 0.0;
        for (int p = lane; p < P_; p += 32)
            a += (double)row[p] * (double)sf[p];
        #pragma unroll
        for (int m = 16; m; m >>= 1) a += __shfl_xor_sync(0xffffffffu, a, m);
        if (lane == 0) d_stimdot[b] = (float)a;
    }
}

// ---------------- K-pack (row-range chunk): bitmask of cc != 0 ----------------
#define PACK_WARPS_CH (BCH_ * NC_ * NW_)               // 64*16*63 = 64512 warps
#define PACK_BLKS_CH  ((PACK_WARPS_CH * 32 + 255) / 256)  // 8064
__global__ void __launch_bounds__(256)
k_pack(const float* __restrict__ cc, int row_base) {
    int gid  = blockIdx.x * blockDim.x + threadIdx.x;
    int wl   = gid >> 5;                 // chunk-local warp
    int lane = gid & 31;
    if (wl >= PACK_WARPS_CH) return;
    int row  = row_base + wl / NW_;
    int word = wl - (wl / NW_) * NW_;
    int elem = word * 32 + lane;
    float v = (elem < NB_) ? cc[(size_t)row * NB_ + elem] : 0.0f;
    unsigned m = __ballot_sync(0xffffffffu, v != 0.0f);
    if (lane == 0) d_bm[row * NWP_ + word] = m;
}

// ---------------- K3: gensig (verified R10 arithmetic; b chunked) ----------------
__global__ void __launch_bounds__(256)
k_gensig(const float* __restrict__ cK,
         const float* __restrict__ bias, int b_base) {
    __shared__ double sKd[NC_ * 256];          // taps zero-padded 250 -> 256
    __shared__ unsigned sbm[NC_ * NWP_];

    const int tid = threadIdx.x;
    const int b   = b_base + blockIdx.y;

    for (int i = tid; i < NC_ * 256; i += 256) {
        int c = i >> 8, k = i & 255;
        sKd[i] = (k < NF_) ? (double)cK[c * NF_ + k] : 0.0;
    }
    for (int i = tid; i < NC_ * NWP_; i += 256)
        sbm[i] = d_bm[b * NC_ * NWP_ + i];
    __syncthreads();

    const int t = blockIdx.x * 256 + tid;
    if (t >= LS_) return;

    const int w0 = t >> 5;
    const int o  = t & 31;

    double a0 = 0.0, a1 = 0.0, a2 = 0.0, a3 = 0.0;
    double a4 = 0.0, a5 = 0.0, a6 = 0.0, a7 = 0.0;
    #pragma unroll 1
    for (int c = 0; c < NC_; ++c) {
        const unsigned* bm = sbm + c * NWP_ + w0;
        const double*   kd = sKd + c * 256;
        unsigned m0 = __funnelshift_r(bm[0], bm[1], o);
        unsigned m1 = __funnelshift_r(bm[1], bm[2], o);
        unsigned m2 = __funnelshift_r(bm[2], bm[3], o);
        unsigned m3 = __funnelshift_r(bm[3], bm[4], o);
        unsigned m4 = __funnelshift_r(bm[4], bm[5], o);
        unsigned m5 = __funnelshift_r(bm[5], bm[6], o);
        unsigned m6 = __funnelshift_r(bm[6], bm[7], o);
        unsigned m7 = __funnelshift_r(bm[7], bm[8], o);
        while (m0) { int i = __ffs(m0) - 1; m0 &= m0 - 1; a0 += kd[  0 + i]; }
        while (m1) { int i = __ffs(m1) - 1; m1 &= m1 - 1; a1 += kd[ 32 + i]; }
        while (m2) { int i = __ffs(m2) - 1; m2 &= m2 - 1; a2 += kd[ 64 + i]; }
        while (m3) { int i = __ffs(m3) - 1; m3 &= m3 - 1; a3 += kd[ 96 + i]; }
        while (m4) { int i = __ffs(m4) - 1; m4 &= m4 - 1; a4 += kd[128 + i]; }
        while (m5) { int i = __ffs(m5) - 1; m5 &= m5 - 1; a5 += kd[160 + i]; }
        while (m6) { int i = __ffs(m6) - 1; m6 &= m6 - 1; a6 += kd[192 + i]; }
        while (m7) { int i = __ffs(m7) - 1; m7 &= m7 - 1; a7 += kd[224 + i]; }
    }
    float coup = (float)(((a0 + a1) + (a2 + a3)) + ((a4 + a5) + (a6 + a7)));
    float sg = __fmul_rn(d_stimdot[b], d_filt[t]);
    sg = __fadd_rn(sg, bias[0]);
    d_gensig[b * LS_ + t] = __fadd_rn(sg, coup);
}

// ---------------- K4: simulation — R12 version verbatim, b chunked ------------
// Chunk = 64 b x 32 warps = 2048 warps -> 1024 blocks of 64 threads.
__global__ void __launch_bounds__(64)
k_sim(const float* __restrict__ init,
      const float* __restrict__ ff,
      const float* __restrict__ u,
      float* __restrict__ out, int b_base) {
    const unsigned FULL = 0xffffffffu;
    const int lane = threadIdx.x & 31;
    const int gwl  = (blockIdx.x * blockDim.x + threadIdx.x) >> 5;  // 0..2047
    const int b    = b_base + (gwl >> 5);    // 32 warps per b
    const int rq   = gwl & 31;
    const int half = lane >> 3;              // 0..3: sequence within the warp
    const int q    = lane & 7;               // lane within the 8-lane group
    const int seq  = b * R_ + rq * 4 + half;

    float f[32], w[32];
    #pragma unroll
    for (int i = 0; i < 32; ++i) {
        int k = q * 32 + i;
        bool valid = (k < NF_);
        f[i] = valid ? ff[k] : 0.0f;
        w[i] = valid ? init[b * NF_ + k] : 0.0f;
    }

    float* orow = out + (size_t)seq * NB_;
    for (int k = q; k < NF_; k += 8)
        orow[k] = init[b * NF_ + k];

    const float* gens = d_gensig + b * LS_;
    const int src_half  = lane & 24;
    const int src_shift = src_half | ((q + 1) & 7);

    for (int t0 = 0; t0 < LS_; t0 += 32) {
        float gval = (t0 + lane < LS_) ? gens[t0 + lane] : 0.0f;
        float uval[4], outv[4];
        #pragma unroll
        for (int m = 0; m < 4; ++m) {
            int t = t0 + 8 * m + q;
            uval[m] = (t < LS_) ? u[(size_t)t * (B_ * R_) + seq] : 0.0f;
            outv[m] = 0.0f;
        }

        #pragma unroll
        for (int s = 0; s < 32; ++s) {
            float a  = w[s & 31]        * f[0];
            float bb = w[(16 + s) & 31] * f[16];
            #pragma unroll
            for (int i = 1; i < 16; ++i) {
                a  = fmaf(w[(i + s) & 31],      f[i],      a);
                bb = fmaf(w[(16 + i + s) & 31], f[16 + i], bb);
            }
            float acc = a + bb;
            acc += __shfl_xor_sync(FULL, acc, 1);
            acc += __shfl_xor_sync(FULL, acc, 2);
            acc += __shfl_xor_sync(FULL, acc, 4);

            float gt = __shfl_sync(FULL, gval, s);
            float ut = __shfl_sync(FULL, uval[s >> 3], src_half | (s & 7));

            float g = gt + acc;
            float e = expf(-g);
            float sig = 1.0f / (1.0f + e);
            float spike = (ut < sig) ? 1.0f : 0.0f;

            if (q == (s & 7)) outv[s >> 3] = spike;

            float inc = __shfl_sync(FULL, w[s & 31], src_shift);
            w[s & 31] = inc;
            if (q == 7) w[(s + 26) & 31] = spike;
        }

        #pragma unroll
        for (int m = 0; m < 4; ++m) {
            int t = t0 + 8 * m + q;
            if (t < LS_) orow[NF_ + t] = outv[m];
        }
    }
}

// ---------------- launch: 2-way fork/join using ONLY built-in streams ----------
extern "C" void kernel_launch(void* const* d_in, const int* in_sizes, int n_in,
                              void* d_out, int out_size) {
    (void)in_sizes; (void)n_in; (void)out_size;
    const float* stim_spat = (const float*)d_in[0];
    const float* stim_time = (const float*)d_in[1];
    const float* init      = (const float*)d_in[2];
    const float* cc        = (const float*)d_in[3];
    const float* sf        = (const float*)d_in[4];
    const float* bias      = (const float*)d_in[5];
    const float* stf       = (const float*)d_in[6];
    const float* ff        = (const float*)d_in[7];
    const float* cK        = (const float*)d_in[8];
    const float* u         = (const float*)d_in[9];
    float* out = (float*)d_out;

    // Built-in second stream (no cudaStreamCreate); timing-disabled events are
    // host-side objects (no device-memory pool). Never destroyed (no frees).
    cudaEvent_t evFork, evJoin;
    cudaEventCreateWithFlags(&evFork, cudaEventDisableTiming);
    cudaEventCreateWithFlags(&evJoin, cudaEventDisableTiming);

    dim3 gg((LS_ + 255) / 256, BCH_);

    // ---- chunk A prep on the captured (legacy) stream ----
    k_small<<<(SMALL_WARPS * 32 + 255) / 256, 256>>>(stim_time, stf,
                                                     stim_spat, sf);
    k_pack<<<PACK_BLKS_CH, 256>>>(cc, 0);
    k_gensig<<<gg, 256>>>(cK, bias, 0);

    // ---- fork: sim chunk A runs on cudaStreamPerThread ----
    cudaEventRecord(evFork, 0);
    cudaStreamWaitEvent(cudaStreamPerThread, evFork, 0);
    k_sim<<<1024, 64, 0, cudaStreamPerThread>>>(init, ff, u, out, 0);
    cudaEventRecord(evJoin, cudaStreamPerThread);

    // ---- chunk B prep + sim overlap with sim A on the legacy stream ----
    k_pack<<<PACK_BLKS_CH, 256>>>(cc, BCH_ * NC_);
    k_gensig<<<gg, 256>>>(cK, bias, BCH_);
    k_sim<<<1024, 64>>>(init, ff, u, out, BCH_);

    // ---- join ----
    cudaStreamWaitEvent(0, evJoin, 0);
}

// round 15
// speedup vs baseline: 1.1244x; 1.1244x over previous
#include <cuda_runtime.h>
#include <math.h>

#define B_   128
#define P_   2048
#define NB_  2000
#define NF_  250
#define NC_  16
#define R_   128
#define LS_  1750      // NB - NF
#define FT_  1751      // NB - NF + 1
#define NW_  63        // 32-bit words covering NB=2000
#define NWP_ 64        // padded row stride in words

// ---------------- scratch (static device globals; no allocations) ----------------
__device__ float d_filt[FT_];
__device__ float d_stimdot[B_];
__device__ float d_gensig[B_ * LS_];
__device__ unsigned d_bm[B_ * NC_ * NWP_];   // bitmask of cc != 0

// ---------------- K-prep: fused pack + filt + stimdot (dispatch by blockIdx) ----
// Pack: one warp handles a 16-word group of one row (16 coalesced loads + 16
// ballots) -> 2048 rows x 4 groups = 8192 warps = 1024 blocks.
#define PACK_BLKS  ((B_ * NC_ * 4 * 32 + 255) / 256)     // 1024
#define FILT_BLKS  ((FT_ * 32 + 255) / 256)              // 219
#define STIM_BLKS  ((B_ * 32 + 255) / 256)               // 16

__global__ void __launch_bounds__(256)
k_prep(const float* __restrict__ cc,
       const float* __restrict__ stim_time,
       const float* __restrict__ stf,
       const float* __restrict__ spat,
       const float* __restrict__ sf) {
    const int blk = blockIdx.x;
    const int lane = threadIdx.x & 31;

    if (blk < PACK_BLKS) {
        int warp = (blk * 256 + threadIdx.x) >> 5;   // 0..8191
        int row  = warp >> 2;                        // 0..2047 (= b*NC + c)
        int wg   = warp & 3;                         // 16-word group
        const float* rp = cc + (size_t)row * NB_;
        #pragma unroll
        for (int k = 0; k < 16; ++k) {
            int word = wg * 16 + k;
            if (word >= NW_) break;                  // group 3 has 15 words
            int elem = word * 32 + lane;
            float v = (elem < NB_) ? rp[elem] : 0.0f;
            unsigned m = __ballot_sync(0xffffffffu, v != 0.0f);
            if (lane == 0) d_bm[row * NWP_ + word] = m;
        }
    } else if (blk < PACK_BLKS + FILT_BLKS) {
        int warp = ((blk - PACK_BLKS) * 256 + threadIdx.x) >> 5;
        if (warp >= FT_) return;
        double a = 0.0;
        #pragma unroll
        for (int i = lane; i < NF_; i += 32)
            a += (double)stim_time[warp + i] * (double)stf[i];
        #pragma unroll
        for (int m = 16; m; m >>= 1) a += __shfl_xor_sync(0xffffffffu, a, m);
        if (lane == 0) d_filt[warp] = (float)a;
    } else {
        int warp = ((blk - PACK_BLKS - FILT_BLKS) * 256 + threadIdx.x) >> 5;
        if (warp >= B_) return;
        const float* row = spat + (size_t)warp * P_;
        double a = 0.0;
        for (int p = lane; p < P_; p += 32)
            a += (double)row[p] * (double)sf[p];
        #pragma unroll
        for (int m = 16; m; m >>= 1) a += __shfl_xor_sync(0xffffffffu, a, m);
        if (lane == 0) d_stimdot[warp] = (float)a;
    }
}

// ---------------- K3: gensig — R10/R12 verified version (frozen) ----------------
__global__ void __launch_bounds__(256)
k_gensig(const float* __restrict__ cK,
         const float* __restrict__ bias) {
    __shared__ double sKd[NC_ * 256];          // taps zero-padded 250 -> 256
    __shared__ unsigned sbm[NC_ * NWP_];

    const int tid = threadIdx.x;
    const int b   = blockIdx.y;

    for (int i = tid; i < NC_ * 256; i += 256) {
        int c = i >> 8, k = i & 255;
        sKd[i] = (k < NF_) ? (double)cK[c * NF_ + k] : 0.0;
    }
    for (int i = tid; i < NC_ * NWP_; i += 256)
        sbm[i] = d_bm[b * NC_ * NWP_ + i];
    __syncthreads();

    const int t = blockIdx.x * 256 + tid;
    if (t >= LS_) return;

    const int w0 = t >> 5;
    const int o  = t & 31;

    double a0 = 0.0, a1 = 0.0, a2 = 0.0, a3 = 0.0;
    double a4 = 0.0, a5 = 0.0, a6 = 0.0, a7 = 0.0;
    #pragma unroll 1
    for (int c = 0; c < NC_; ++c) {
        const unsigned* bm = sbm + c * NWP_ + w0;
        const double*   kd = sKd + c * 256;
        unsigned m0 = __funnelshift_r(bm[0], bm[1], o);
        unsigned m1 = __funnelshift_r(bm[1], bm[2], o);
        unsigned m2 = __funnelshift_r(bm[2], bm[3], o);
        unsigned m3 = __funnelshift_r(bm[3], bm[4], o);
        unsigned m4 = __funnelshift_r(bm[4], bm[5], o);
        unsigned m5 = __funnelshift_r(bm[5], bm[6], o);
        unsigned m6 = __funnelshift_r(bm[6], bm[7], o);
        unsigned m7 = __funnelshift_r(bm[7], bm[8], o);
        while (m0) { int i = __ffs(m0) - 1; m0 &= m0 - 1; a0 += kd[  0 + i]; }
        while (m1) { int i = __ffs(m1) - 1; m1 &= m1 - 1; a1 += kd[ 32 + i]; }
        while (m2) { int i = __ffs(m2) - 1; m2 &= m2 - 1; a2 += kd[ 64 + i]; }
        while (m3) { int i = __ffs(m3) - 1; m3 &= m3 - 1; a3 += kd[ 96 + i]; }
        while (m4) { int i = __ffs(m4) - 1; m4 &= m4 - 1; a4 += kd[128 + i]; }
        while (m5) { int i = __ffs(m5) - 1; m5 &= m5 - 1; a5 += kd[160 + i]; }
        while (m6) { int i = __ffs(m6) - 1; m6 &= m6 - 1; a6 += kd[192 + i]; }
        while (m7) { int i = __ffs(m7) - 1; m7 &= m7 - 1; a7 += kd[224 + i]; }
    }
    float coup = (float)(((a0 + a1) + (a2 + a3)) + ((a4 + a5) + (a6 + a7)));
    float sg = __fmul_rn(d_stimdot[b], d_filt[t]);
    sg = __fadd_rn(sg, bias[0]);
    d_gensig[b * LS_ + t] = __fadd_rn(sg, coup);
}

// ---------------- K4: simulation — R12 version verbatim (frozen) ----------------
__global__ void __launch_bounds__(64)
k_sim(const float* __restrict__ init,
      const float* __restrict__ ff,
      const float* __restrict__ u,
      float* __restrict__ out) {
    const unsigned FULL = 0xffffffffu;
    const int lane = threadIdx.x & 31;
    const int gw   = (blockIdx.x * blockDim.x + threadIdx.x) >> 5;  // 0..4095
    const int b    = gw >> 5;         // 32 warps per b
    const int rq   = gw & 31;
    const int half = lane >> 3;       // 0..3: sequence within the warp
    const int q    = lane & 7;        // lane within the 8-lane group
    const int seq  = b * R_ + rq * 4 + half;

    float f[32], w[32];
    #pragma unroll
    for (int i = 0; i < 32; ++i) {
        int k = q * 32 + i;
        bool valid = (k < NF_);
        f[i] = valid ? ff[k] : 0.0f;
        w[i] = valid ? init[b * NF_ + k] : 0.0f;
    }

    float* orow = out + (size_t)seq * NB_;
    for (int k = q; k < NF_; k += 8)
        orow[k] = init[b * NF_ + k];

    const float* gens = d_gensig + b * LS_;
    const int src_half  = lane & 24;
    const int src_shift = src_half | ((q + 1) & 7);

    for (int t0 = 0; t0 < LS_; t0 += 32) {
        float gval = (t0 + lane < LS_) ? gens[t0 + lane] : 0.0f;
        float uval[4], outv[4];
        #pragma unroll
        for (int m = 0; m < 4; ++m) {
            int t = t0 + 8 * m + q;
            uval[m] = (t < LS_) ? u[(size_t)t * (B_ * R_) + seq] : 0.0f;
            outv[m] = 0.0f;
        }

        #pragma unroll
        for (int s = 0; s < 32; ++s) {
            float a  = w[s & 31]        * f[0];
            float bb = w[(16 + s) & 31] * f[16];
            #pragma unroll
            for (int i = 1; i < 16; ++i) {
                a  = fmaf(w[(i + s) & 31],      f[i],      a);
                bb = fmaf(w[(16 + i + s) & 31], f[16 + i], bb);
            }
            float acc = a + bb;
            acc += __shfl_xor_sync(FULL, acc, 1);
            acc += __shfl_xor_sync(FULL, acc, 2);
            acc += __shfl_xor_sync(FULL, acc, 4);

            float gt = __shfl_sync(FULL, gval, s);
            float ut = __shfl_sync(FULL, uval[s >> 3], src_half | (s & 7));

            float g = gt + acc;
            float e = expf(-g);
            float sig = 1.0f / (1.0f + e);
            float spike = (ut < sig) ? 1.0f : 0.0f;

            if (q == (s & 7)) outv[s >> 3] = spike;

            float inc = __shfl_sync(FULL, w[s & 31], src_shift);
            w[s & 31] = inc;
            if (q == 7) w[(s + 26) & 31] = spike;
        }

        #pragma unroll
        for (int m = 0; m < 4; ++m) {
            int t = t0 + 8 * m + q;
            if (t < LS_) orow[NF_ + t] = outv[m];
        }
    }
}

// ---------------- launch ----------------
extern "C" void kernel_launch(void* const* d_in, const int* in_sizes, int n_in,
                              void* d_out, int out_size) {
    (void)in_sizes; (void)n_in; (void)out_size;
    const float* stim_spat = (const float*)d_in[0];
    const float* stim_time = (const float*)d_in[1];
    const float* init      = (const float*)d_in[2];
    const float* cc        = (const float*)d_in[3];
    const float* sf        = (const float*)d_in[4];
    const float* bias      = (const float*)d_in[5];
    const float* stf       = (const float*)d_in[6];
    const float* ff        = (const float*)d_in[7];
    const float* cK        = (const float*)d_in[8];
    const float* u         = (const float*)d_in[9];
    float* out = (float*)d_out;

    // fused prep: pack (16 words/warp) + filt + stimdot
    k_prep<<<PACK_BLKS + FILT_BLKS + STIM_BLKS, 256>>>(cc, stim_time, stf,
                                                       stim_spat, sf);

    dim3 g3((LS_ + 255) / 256, B_);
    k_gensig<<<g3, 256>>>(cK, bias);

    // 4096 warps (4 sequences each) -> 2048 blocks of 64 threads
    k_sim<<<2048, 64>>>(init, ff, u, out);
}

// round 16
// speedup vs baseline: 1.1413x; 1.0151x over previous
#include <cuda_runtime.h>
#include <math.h>

#define B_   128
#define P_   2048
#define NB_  2000
#define NF_  250
#define NC_  16
#define R_   128
#define LS_  1750      // NB - NF
#define FT_  1751      // NB - NF + 1
#define NW_  63        // 32-bit words covering NB=2000
#define NWP_ 64        // padded row stride in words

// ---- PDL intrinsics (sm_90+) ----
__device__ __forceinline__ void gdc_wait() {
    asm volatile("griddepcontrol.wait;" ::: "memory");
}
__device__ __forceinline__ void gdc_launch() {
    asm volatile("griddepcontrol.launch_dependents;" ::: "memory");
}

// ---------------- scratch (static device globals; no allocations) ----------------
__device__ float d_filt[FT_];
__device__ float d_stimdot[B_];
__device__ float d_gensig[B_ * LS_];
__device__ unsigned d_bm[B_ * NC_ * NWP_];   // bitmask of cc != 0

// ---------------- K-prep: fused pack + filt + stimdot (dispatch by blockIdx) ----
#define PACK_BLKS  ((B_ * NC_ * 4 * 32 + 255) / 256)     // 1024
#define FILT_BLKS  ((FT_ * 32 + 255) / 256)              // 219
#define STIM_BLKS  ((B_ * 32 + 255) / 256)               // 16
#define PREP_BLKS  (PACK_BLKS + FILT_BLKS + STIM_BLKS)

__global__ void __launch_bounds__(256)
k_prep(const float* __restrict__ cc,
       const float* __restrict__ stim_time,
       const float* __restrict__ stf,
       const float* __restrict__ spat,
       const float* __restrict__ sf) {
    const int blk = blockIdx.x;
    const int lane = threadIdx.x & 31;

    // let gensig get scheduled early (it waits before reading our outputs)
    gdc_launch();

    if (blk < PACK_BLKS) {
        int warp = (blk * 256 + threadIdx.x) >> 5;   // 0..8191
        int row  = warp >> 2;                        // 0..2047 (= b*NC + c)
        int wg   = warp & 3;                         // 16-word group
        const float* rp = cc + (size_t)row * NB_;
        #pragma unroll
        for (int k = 0; k < 16; ++k) {
            int word = wg * 16 + k;
            if (word >= NW_) break;                  // group 3 has 15 words
            int elem = word * 32 + lane;
            float v = (elem < NB_) ? rp[elem] : 0.0f;
            unsigned m = __ballot_sync(0xffffffffu, v != 0.0f);
            if (lane == 0) d_bm[row * NWP_ + word] = m;
        }
    } else if (blk < PACK_BLKS + FILT_BLKS) {
        int warp = ((blk - PACK_BLKS) * 256 + threadIdx.x) >> 5;
        if (warp >= FT_) return;
        double a = 0.0;
        #pragma unroll
        for (int i = lane; i < NF_; i += 32)
            a += (double)stim_time[warp + i] * (double)stf[i];
        #pragma unroll
        for (int m = 16; m; m >>= 1) a += __shfl_xor_sync(0xffffffffu, a, m);
        if (lane == 0) d_filt[warp] = (float)a;
    } else {
        int warp = ((blk - PACK_BLKS - FILT_BLKS) * 256 + threadIdx.x) >> 5;
        if (warp >= B_) return;
        const float* row = spat + (size_t)warp * P_;
        double a = 0.0;
        for (int p = lane; p < P_; p += 32)
            a += (double)row[p] * (double)sf[p];
        #pragma unroll
        for (int m = 16; m; m >>= 1) a += __shfl_xor_sync(0xffffffffu, a, m);
        if (lane == 0) d_stimdot[warp] = (float)a;
    }
}

// ---------------- K3: gensig — R10/R12 verified arithmetic + PDL ----------------
__global__ void __launch_bounds__(256)
k_gensig(const float* __restrict__ cK,
         const float* __restrict__ bias) {
    __shared__ double sKd[NC_ * 256];          // taps zero-padded 250 -> 256
    __shared__ unsigned sbm[NC_ * NWP_];

    const int tid = threadIdx.x;
    const int b   = blockIdx.y;

    // let sim get scheduled early (it waits before reading d_gensig)
    gdc_launch();

    // prologue: depends only on the cK input — overlaps prep's tail
    for (int i = tid; i < NC_ * 256; i += 256) {
        int c = i >> 8, k = i & 255;
        sKd[i] = (k < NF_) ? (double)cK[c * NF_ + k] : 0.0;
    }

    // everything below reads prep's outputs (d_bm, d_filt, d_stimdot)
    gdc_wait();

    for (int i = tid; i < NC_ * NWP_; i += 256)
        sbm[i] = d_bm[b * NC_ * NWP_ + i];
    __syncthreads();

    const int t = blockIdx.x * 256 + tid;
    if (t >= LS_) return;

    const int w0 = t >> 5;
    const int o  = t & 31;

    double a0 = 0.0, a1 = 0.0, a2 = 0.0, a3 = 0.0;
    double a4 = 0.0, a5 = 0.0, a6 = 0.0, a7 = 0.0;
    #pragma unroll 1
    for (int c = 0; c < NC_; ++c) {
        const unsigned* bm = sbm + c * NWP_ + w0;
        const double*   kd = sKd + c * 256;
        unsigned m0 = __funnelshift_r(bm[0], bm[1], o);
        unsigned m1 = __funnelshift_r(bm[1], bm[2], o);
        unsigned m2 = __funnelshift_r(bm[2], bm[3], o);
        unsigned m3 = __funnelshift_r(bm[3], bm[4], o);
        unsigned m4 = __funnelshift_r(bm[4], bm[5], o);
        unsigned m5 = __funnelshift_r(bm[5], bm[6], o);
        unsigned m6 = __funnelshift_r(bm[6], bm[7], o);
        unsigned m7 = __funnelshift_r(bm[7], bm[8], o);
        while (m0) { int i = __ffs(m0) - 1; m0 &= m0 - 1; a0 += kd[  0 + i]; }
        while (m1) { int i = __ffs(m1) - 1; m1 &= m1 - 1; a1 += kd[ 32 + i]; }
        while (m2) { int i = __ffs(m2) - 1; m2 &= m2 - 1; a2 += kd[ 64 + i]; }
        while (m3) { int i = __ffs(m3) - 1; m3 &= m3 - 1; a3 += kd[ 96 + i]; }
        while (m4) { int i = __ffs(m4) - 1; m4 &= m4 - 1; a4 += kd[128 + i]; }
        while (m5) { int i = __ffs(m5) - 1; m5 &= m5 - 1; a5 += kd[160 + i]; }
        while (m6) { int i = __ffs(m6) - 1; m6 &= m6 - 1; a6 += kd[192 + i]; }
        while (m7) { int i = __ffs(m7) - 1; m7 &= m7 - 1; a7 += kd[224 + i]; }
    }
    float coup = (float)(((a0 + a1) + (a2 + a3)) + ((a4 + a5) + (a6 + a7)));
    float sg = __fmul_rn(d_stimdot[b], d_filt[t]);
    sg = __fadd_rn(sg, bias[0]);
    d_gensig[b * LS_ + t] = __fadd_rn(sg, coup);
}

// ---------------- K4: simulation — R12 arithmetic verbatim + PDL ----------------
__global__ void __launch_bounds__(64)
k_sim(const float* __restrict__ init,
      const float* __restrict__ ff,
      const float* __restrict__ u,
      float* __restrict__ out) {
    const unsigned FULL = 0xffffffffu;
    const int lane = threadIdx.x & 31;
    const int gw   = (blockIdx.x * blockDim.x + threadIdx.x) >> 5;  // 0..4095
    const int b    = gw >> 5;         // 32 warps per b
    const int rq   = gw & 31;
    const int half = lane >> 3;       // 0..3: sequence within the warp
    const int q    = lane & 7;        // lane within the 8-lane group
    const int seq  = b * R_ + rq * 4 + half;

    // prologue: depends only on harness inputs (init, ff) — overlaps gensig
    float f[32], w[32];
    #pragma unroll
    for (int i = 0; i < 32; ++i) {
        int k = q * 32 + i;
        bool valid = (k < NF_);
        f[i] = valid ? ff[k] : 0.0f;
        w[i] = valid ? init[b * NF_ + k] : 0.0f;
    }

    float* orow = out + (size_t)seq * NB_;
    for (int k = q; k < NF_; k += 8)
        orow[k] = init[b * NF_ + k];

    // main loop reads d_gensig — wait for gensig grid completion
    gdc_wait();

    const float* gens = d_gensig + b * LS_;
    const int src_half  = lane & 24;
    const int src_shift = src_half | ((q + 1) & 7);

    for (int t0 = 0; t0 < LS_; t0 += 32) {
        float gval = (t0 + lane < LS_) ? gens[t0 + lane] : 0.0f;
        float uval[4], outv[4];
        #pragma unroll
        for (int m = 0; m < 4; ++m) {
            int t = t0 + 8 * m + q;
            uval[m] = (t < LS_) ? u[(size_t)t * (B_ * R_) + seq] : 0.0f;
            outv[m] = 0.0f;
        }

        #pragma unroll
        for (int s = 0; s < 32; ++s) {
            float a  = w[s & 31]        * f[0];
            float bb = w[(16 + s) & 31] * f[16];
            #pragma unroll
            for (int i = 1; i < 16; ++i) {
                a  = fmaf(w[(i + s) & 31],      f[i],      a);
                bb = fmaf(w[(16 + i + s) & 31], f[16 + i], bb);
            }
            float acc = a + bb;
            acc += __shfl_xor_sync(FULL, acc, 1);
            acc += __shfl_xor_sync(FULL, acc, 2);
            acc += __shfl_xor_sync(FULL, acc, 4);

            float gt = __shfl_sync(FULL, gval, s);
            float ut = __shfl_sync(FULL, uval[s >> 3], src_half | (s & 7));

            float g = gt + acc;
            float e = expf(-g);
            float sig = 1.0f / (1.0f + e);
            float spike = (ut < sig) ? 1.0f : 0.0f;

            if (q == (s & 7)) outv[s >> 3] = spike;

            float inc = __shfl_sync(FULL, w[s & 31], src_shift);
            w[s & 31] = inc;
            if (q == 7) w[(s + 26) & 31] = spike;
        }

        #pragma unroll
        for (int m = 0; m < 4; ++m) {
            int t = t0 + 8 * m + q;
            if (t < LS_) orow[NF_ + t] = outv[m];
        }
    }
}

// ---------------- launch: serial stream + PDL early-launch edges ----------------
extern "C" void kernel_launch(void* const* d_in, const int* in_sizes, int n_in,
                              void* d_out, int out_size) {
    (void)in_sizes; (void)n_in; (void)out_size;
    const float* stim_spat = (const float*)d_in[0];
    const float* stim_time = (const float*)d_in[1];
    const float* init      = (const float*)d_in[2];
    const float* cc        = (const float*)d_in[3];
    const float* sf        = (const float*)d_in[4];
    const float* bias      = (const float*)d_in[5];
    const float* stf       = (const float*)d_in[6];
    const float* ff        = (const float*)d_in[7];
    const float* cK        = (const float*)d_in[8];
    const float* u         = (const float*)d_in[9];
    float* out = (float*)d_out;

    // prep: normal launch
    k_prep<<<PREP_BLKS, 256>>>(cc, stim_time, stf, stim_spat, sf);

    cudaLaunchAttribute pdl[1];
    pdl[0].id = cudaLaunchAttributeProgrammaticStreamSerialization;
    pdl[0].val.programmaticStreamSerializationAllowed = 1;

    // gensig: PDL-dependent on prep
    {
        cudaLaunchConfig_t cfg = {};
        cfg.gridDim  = dim3((LS_ + 255) / 256, B_);
        cfg.blockDim = dim3(256, 1, 1);
        cfg.attrs = pdl;
        cfg.numAttrs = 1;
        cudaLaunchKernelEx(&cfg, k_gensig, cK, bias);
    }

    // sim: PDL-dependent on gensig
    {
        cudaLaunchConfig_t cfg = {};
        cfg.gridDim  = dim3(2048, 1, 1);
        cfg.blockDim = dim3(64, 1, 1);
        cfg.attrs = pdl;
        cfg.numAttrs = 1;
        cudaLaunchKernelEx(&cfg, k_sim, init, ff, u, out);
    }
}

// round 17
// speedup vs baseline: 1.1438x; 1.0022x over previous
#include <cuda_runtime.h>
#include <math.h>

#define B_   128
#define P_   2048
#define NB_  2000
#define NF_  250
#define NC_  16
#define R_   128
#define LS_  1750      // NB - NF
#define FT_  1751      // NB - NF + 1
#define NW_  63        // 32-bit words covering NB=2000
#define NWP_ 64        // padded row stride in words

// ---- PDL intrinsics (sm_90+) ----
__device__ __forceinline__ void gdc_wait() {
    asm volatile("griddepcontrol.wait;" ::: "memory");
}
__device__ __forceinline__ void gdc_launch() {
    asm volatile("griddepcontrol.launch_dependents;" ::: "memory");
}

// ---------------- scratch (static device globals; no allocations) ----------------
__device__ float d_filt[FT_];
__device__ float d_stimdot[B_];
__device__ float d_gensig[B_ * LS_];
__device__ unsigned d_bm[B_ * NC_ * NWP_];   // bitmask of cc != 0

// ---------------- K-prep: fused pack + filt + stimdot ----------------
#define PACK_BLKS  ((B_ * NC_ * 4 * 32 + 255) / 256)     // 1024
#define FILT_BLKS  ((FT_ * 32 + 255) / 256)              // 219
#define STIM_BLKS  ((B_ * 32 + 255) / 256)               // 16
#define PREP_BLKS  (PACK_BLKS + FILT_BLKS + STIM_BLKS)

__global__ void __launch_bounds__(256)
k_prep(const float* __restrict__ cc,
       const float* __restrict__ stim_time,
       const float* __restrict__ stf,
       const float* __restrict__ spat,
       const float* __restrict__ sf) {
    const int blk = blockIdx.x;
    const int lane = threadIdx.x & 31;

    gdc_launch();

    if (blk < PACK_BLKS) {
        int warp = (blk * 256 + threadIdx.x) >> 5;   // 0..8191
        int row  = warp >> 2;                        // 0..2047 (= b*NC + c)
        int wg   = warp & 3;                         // 16-word group
        const float* rp = cc + (size_t)row * NB_;
        #pragma unroll
        for (int k = 0; k < 16; ++k) {
            int word = wg * 16 + k;
            if (word >= NW_) break;
            int elem = word * 32 + lane;
            float v = (elem < NB_) ? rp[elem] : 0.0f;
            unsigned m = __ballot_sync(0xffffffffu, v != 0.0f);
            if (lane == 0) d_bm[row * NWP_ + word] = m;
        }
    } else if (blk < PACK_BLKS + FILT_BLKS) {
        int warp = ((blk - PACK_BLKS) * 256 + threadIdx.x) >> 5;
        if (warp >= FT_) return;
        double a = 0.0;
        #pragma unroll
        for (int i = lane; i < NF_; i += 32)
            a += (double)stim_time[warp + i] * (double)stf[i];
        #pragma unroll
        for (int m = 16; m; m >>= 1) a += __shfl_xor_sync(0xffffffffu, a, m);
        if (lane == 0) d_filt[warp] = (float)a;
    } else {
        int warp = ((blk - PACK_BLKS - FILT_BLKS) * 256 + threadIdx.x) >> 5;
        if (warp >= B_) return;
        const float* row = spat + (size_t)warp * P_;
        double a = 0.0;
        for (int p = lane; p < P_; p += 32)
            a += (double)row[p] * (double)sf[p];
        #pragma unroll
        for (int m = 16; m; m >>= 1) a += __shfl_xor_sync(0xffffffffu, a, m);
        if (lane == 0) d_stimdot[warp] = (float)a;
    }
}

// ---------------- K3: gensig — verified arithmetic + PDL ----------------
__global__ void __launch_bounds__(256)
k_gensig(const float* __restrict__ cK,
         const float* __restrict__ bias) {
    __shared__ double sKd[NC_ * 256];
    __shared__ unsigned sbm[NC_ * NWP_];

    const int tid = threadIdx.x;
    const int b   = blockIdx.y;

    gdc_launch();

    // prologue: depends only on cK — overlaps prep's tail
    for (int i = tid; i < NC_ * 256; i += 256) {
        int c = i >> 8, k = i & 255;
        sKd[i] = (k < NF_) ? (double)cK[c * NF_ + k] : 0.0;
    }

    gdc_wait();   // everything below reads prep outputs

    for (int i = tid; i < NC_ * NWP_; i += 256)
        sbm[i] = d_bm[b * NC_ * NWP_ + i];
    __syncthreads();

    const int t = blockIdx.x * 256 + tid;
    if (t >= LS_) return;

    const int w0 = t >> 5;
    const int o  = t & 31;

    double a0 = 0.0, a1 = 0.0, a2 = 0.0, a3 = 0.0;
    double a4 = 0.0, a5 = 0.0, a6 = 0.0, a7 = 0.0;
    #pragma unroll 1
    for (int c = 0; c < NC_; ++c) {
        const unsigned* bm = sbm + c * NWP_ + w0;
        const double*   kd = sKd + c * 256;
        unsigned m0 = __funnelshift_r(bm[0], bm[1], o);
        unsigned m1 = __funnelshift_r(bm[1], bm[2], o);
        unsigned m2 = __funnelshift_r(bm[2], bm[3], o);
        unsigned m3 = __funnelshift_r(bm[3], bm[4], o);
        unsigned m4 = __funnelshift_r(bm[4], bm[5], o);
        unsigned m5 = __funnelshift_r(bm[5], bm[6], o);
        unsigned m6 = __funnelshift_r(bm[6], bm[7], o);
        unsigned m7 = __funnelshift_r(bm[7], bm[8], o);
        while (m0) { int i = __ffs(m0) - 1; m0 &= m0 - 1; a0 += kd[  0 + i]; }
        while (m1) { int i = __ffs(m1) - 1; m1 &= m1 - 1; a1 += kd[ 32 + i]; }
        while (m2) { int i = __ffs(m2) - 1; m2 &= m2 - 1; a2 += kd[ 64 + i]; }
        while (m3) { int i = __ffs(m3) - 1; m3 &= m3 - 1; a3 += kd[ 96 + i]; }
        while (m4) { int i = __ffs(m4) - 1; m4 &= m4 - 1; a4 += kd[128 + i]; }
        while (m5) { int i = __ffs(m5) - 1; m5 &= m5 - 1; a5 += kd[160 + i]; }
        while (m6) { int i = __ffs(m6) - 1; m6 &= m6 - 1; a6 += kd[192 + i]; }
        while (m7) { int i = __ffs(m7) - 1; m7 &= m7 - 1; a7 += kd[224 + i]; }
    }
    float coup = (float)(((a0 + a1) + (a2 + a3)) + ((a4 + a5) + (a6 + a7)));
    float sg = __fmul_rn(d_stimdot[b], d_filt[t]);
    sg = __fadd_rn(sg, bias[0]);
    d_gensig[b * LS_ + t] = __fadd_rn(sg, coup);
}

// ---------------- K4: simulation — frozen arithmetic + block-input prefetch ----
// Identical float ops/ordering to the verified chain; the only change is that
// each 32-step block's gval/uval loads are issued one block EARLY (double
// buffer), hiding their ~577-cyc DRAM latency under the previous block's
// compute. u/gens are never written by this kernel -> same values loaded.
__global__ void __launch_bounds__(64)
k_sim(const float* __restrict__ init,
      const float* __restrict__ ff,
      const float* __restrict__ u,
      float* __restrict__ out) {
    const unsigned FULL = 0xffffffffu;
    const int lane = threadIdx.x & 31;
    const int gw   = (blockIdx.x * blockDim.x + threadIdx.x) >> 5;  // 0..4095
    const int b    = gw >> 5;         // 32 warps per b
    const int rq   = gw & 31;
    const int half = lane >> 3;       // 0..3: sequence within the warp
    const int q    = lane & 7;        // lane within the 8-lane group
    const int seq  = b * R_ + rq * 4 + half;

    // prologue: depends only on harness inputs — overlaps gensig via PDL
    float f[32], w[32];
    #pragma unroll
    for (int i = 0; i < 32; ++i) {
        int k = q * 32 + i;
        bool valid = (k < NF_);
        f[i] = valid ? ff[k] : 0.0f;
        w[i] = valid ? init[b * NF_ + k] : 0.0f;
    }

    float* orow = out + (size_t)seq * NB_;
    for (int k = q; k < NF_; k += 8)
        orow[k] = init[b * NF_ + k];

    // u reads don't depend on gensig: prefetch block 0 BEFORE the wait
    float uval[4];
    #pragma unroll
    for (int m = 0; m < 4; ++m) {
        int t = 8 * m + q;
        uval[m] = (t < LS_) ? u[(size_t)t * (B_ * R_) + seq] : 0.0f;
    }

    gdc_wait();   // main loop reads d_gensig

    const float* gens = d_gensig + b * LS_;
    const int src_half  = lane & 24;
    const int src_shift = src_half | ((q + 1) & 7);

    float gval = (lane < LS_) ? gens[lane] : 0.0f;

    for (int t0 = 0; t0 < LS_; t0 += 32) {
        // ---- prefetch next block's inputs (consumed ~5800 cycles later) ----
        int t1 = t0 + 32;
        float gval_n = (t1 + lane < LS_) ? gens[t1 + lane] : 0.0f;
        float uval_n[4];
        #pragma unroll
        for (int m = 0; m < 4; ++m) {
            int t = t1 + 8 * m + q;
            uval_n[m] = (t < LS_) ? u[(size_t)t * (B_ * R_) + seq] : 0.0f;
        }

        float outv[4];
        outv[0] = outv[1] = outv[2] = outv[3] = 0.0f;

        #pragma unroll
        for (int s = 0; s < 32; ++s) {
            float a  = w[s & 31]        * f[0];
            float bb = w[(16 + s) & 31] * f[16];
            #pragma unroll
            for (int i = 1; i < 16; ++i) {
                a  = fmaf(w[(i + s) & 31],      f[i],      a);
                bb = fmaf(w[(16 + i + s) & 31], f[16 + i], bb);
            }
            float acc = a + bb;
            acc += __shfl_xor_sync(FULL, acc, 1);
            acc += __shfl_xor_sync(FULL, acc, 2);
            acc += __shfl_xor_sync(FULL, acc, 4);

            float gt = __shfl_sync(FULL, gval, s);
            float ut = __shfl_sync(FULL, uval[s >> 3], src_half | (s & 7));

            float g = gt + acc;
            float e = expf(-g);
            float sig = 1.0f / (1.0f + e);
            float spike = (ut < sig) ? 1.0f : 0.0f;

            if (q == (s & 7)) outv[s >> 3] = spike;

            float inc = __shfl_sync(FULL, w[s & 31], src_shift);
            w[s & 31] = inc;
            if (q == 7) w[(s + 26) & 31] = spike;
        }

        #pragma unroll
        for (int m = 0; m < 4; ++m) {
            int t = t0 + 8 * m + q;
            if (t < LS_) orow[NF_ + t] = outv[m];
        }

        gval = gval_n;
        #pragma unroll
        for (int m = 0; m < 4; ++m) uval[m] = uval_n[m];
    }
}

// ---------------- launch: serial stream + PDL early-launch edges ----------------
extern "C" void kernel_launch(void* const* d_in, const int* in_sizes, int n_in,
                              void* d_out, int out_size) {
    (void)in_sizes; (void)n_in; (void)out_size;
    const float* stim_spat = (const float*)d_in[0];
    const float* stim_time = (const float*)d_in[1];
    const float* init      = (const float*)d_in[2];
    const float* cc        = (const float*)d_in[3];
    const float* sf        = (const float*)d_in[4];
    const float* bias      = (const float*)d_in[5];
    const float* stf       = (const float*)d_in[6];
    const float* ff        = (const float*)d_in[7];
    const float* cK        = (const float*)d_in[8];
    const float* u         = (const float*)d_in[9];
    float* out = (float*)d_out;

    k_prep<<<PREP_BLKS, 256>>>(cc, stim_time, stf, stim_spat, sf);

    cudaLaunchAttribute pdl[1];
    pdl[0].id = cudaLaunchAttributeProgrammaticStreamSerialization;
    pdl[0].val.programmaticStreamSerializationAllowed = 1;

    {
        cudaLaunchConfig_t cfg = {};
        cfg.gridDim  = dim3((LS_ + 255) / 256, B_);
        cfg.blockDim = dim3(256, 1, 1);
        cfg.attrs = pdl;
        cfg.numAttrs = 1;
        cudaLaunchKernelEx(&cfg, k_gensig, cK, bias);
    }
    {
        cudaLaunchConfig_t cfg = {};
        cfg.gridDim  = dim3(2048, 1, 1);
        cfg.blockDim = dim3(64, 1, 1);
        cfg.attrs = pdl;
        cfg.numAttrs = 1;
        cudaLaunchKernelEx(&cfg, k_sim, init, ff, u, out);
    }
}